// round 8
// baseline (speedup 1.0000x reference)
#include <cuda_runtime.h>
#include <math.h>
#include <stdint.h>

#define BB 8
#define NN 2048
#define FD 256
#define KK 205
#define KMAX 256
#define LMAX 128
#define SCAP 32
#define FULLM 0xFFFFFFFFu

// output layout (float32): x_c | coarse | S | topi
#define XC_OFF ((size_t)0)
#define CO_OFF ((size_t)BB * NN * FD)
#define S_OFF  (CO_OFF + (size_t)BB * NN * NN)
#define TI_OFF (S_OFF + (size_t)BB * NN * NN)

// ---- scratch (static device globals; no allocation) ----
__device__ float g_dg[BB][NN];
__device__ float g_rowfac[BB][NN];
__device__ float g_y[BB][NN];
__device__ float g_alpha[BB][NN];
__device__ float g_ca[BB][NN];
__device__ float g_invr[BB][NN];
__device__ int   g_colidx[BB][NN];
__device__ int   g_sup[BB][KMAX];
__device__ int   g_nsup[BB];
__device__ int   g_adjcnt[BB][NN];
__device__ int   g_adjk[BB][NN][LMAX];
__device__ float g_adja[BB][NN][LMAX];
__device__ int   g_scnt[BB][NN];          // sparse Sc row counts
__device__ uint2 g_sent[BB][NN][SCAP];    // sparse Sc row entries (slot j, val)
__device__ float g_T[BB][NN][KMAX];       // T = adj @ Sc  (slot-indexed)

// ---------------- kA: single adj pass: rowsum + nnz extraction + y = x@W ----
__global__ void kA_scan(const float* __restrict__ x,
                        const float* __restrict__ adj,
                        const float* __restrict__ W) {
    int bid = blockIdx.x;
    int b = bid >> 11, n = bid & (NN - 1);
    int t = threadIdx.x;
    int wid = t >> 5, lane = t & 31;
    const float4* arow = (const float4*)(adj + ((size_t)b * NN + n) * NN);
    float loc_a[8]; int loc_k[8];
    int cnt = 0;
    float s = 0.f;
    #pragma unroll
    for (int q = 0; q < 2; q++) {
        float4 v = arow[t * 2 + q];
        int kbase = t * 8 + q * 4;
        float va[4] = {v.x, v.y, v.z, v.w};
        #pragma unroll
        for (int i = 0; i < 4; i++) {
            float a = va[i];
            s += a;
            if (a != 0.f) { loc_a[cnt] = a; loc_k[cnt] = kbase + i; cnt++; }
        }
    }
    float yv = x[((size_t)b * NN + n) * FD + t] * W[t];

    int pre = cnt;
    #pragma unroll
    for (int o = 1; o < 32; o <<= 1) {
        int v = __shfl_up_sync(FULLM, pre, o);
        if (lane >= o) pre += v;
    }
    float ssum = s, ysum = yv;
    #pragma unroll
    for (int o = 16; o > 0; o >>= 1) {
        ssum += __shfl_down_sync(FULLM, ssum, o);
        ysum += __shfl_down_sync(FULLM, ysum, o);
    }
    __shared__ int wtot[8];
    __shared__ float ws[8], wy[8];
    if (lane == 31) wtot[wid] = pre;
    if (lane == 0) { ws[wid] = ssum; wy[wid] = ysum; }
    __syncthreads();
    int base = 0;
    #pragma unroll
    for (int w = 0; w < 8; w++) base += (w < wid) ? wtot[w] : 0;
    int off = base + pre - cnt;
    #pragma unroll
    for (int i = 0; i < 8; i++) {
        if (i < cnt) {
            int p = off + i;
            if (p < LMAX) { g_adjk[b][n][p] = loc_k[i]; g_adja[b][n][p] = loc_a[i]; }
        }
    }
    if (t == 0) {
        int total = wtot[0] + wtot[1] + wtot[2] + wtot[3]
                  + wtot[4] + wtot[5] + wtot[6] + wtot[7];
        g_adjcnt[b][n] = (total > LMAX) ? LMAX : total;
        float rs = ((ws[0] + ws[1]) + (ws[2] + ws[3])) + ((ws[4] + ws[5]) + (ws[6] + ws[7]));
        float dg = rsqrtf(1.0f + rs);
        g_dg[b][n] = dg;
        g_rowfac[b][n] = (rs > 0.f) ? dg : 0.f;
        g_y[b][n] = ((wy[0] + wy[1]) + (wy[2] + wy[3])) + ((wy[4] + wy[5]) + (wy[6] + wy[7]));
    }
}

// ---------------- kB: alpha = sigmoid(z^2) ----------------
__global__ void kB_alpha(const float* __restrict__ bias) {
    int gw = blockIdx.x * 8 + (threadIdx.x >> 5);
    int b = gw >> 11, n = gw & (NN - 1);
    int lane = threadIdx.x & 31;
    int cnt = g_adjcnt[b][n];
    float dot = 0.f;
    for (int i = lane; i < cnt; i += 32) {
        int k = g_adjk[b][n][i];
        dot += g_adja[b][n][i] * g_dg[b][k] * g_y[b][k];
    }
    #pragma unroll
    for (int o = 16; o > 0; o >>= 1) dot += __shfl_down_sync(FULLM, dot, o);
    if (lane == 0) {
        float dg = g_dg[b][n];
        float z = dg * (dot + dg * g_y[b][n]) + bias[0];
        float zz = z * z;
        g_alpha[b][n] = 1.0f / (1.0f + expf(-zz));
    }
}

// ---------------- k3: top-k sort + cut + support ----------------
__global__ void k3_topk(float* __restrict__ out_topi) {
    int b = blockIdx.x;
    int t = threadIdx.x;  // 1024
    __shared__ unsigned long long key[NN];
    for (int i = t; i < NN; i += 1024) {
        unsigned int vb = __float_as_uint(g_alpha[b][i]);
        key[i] = ((unsigned long long)vb << 11) | (unsigned)(NN - 1 - i);
    }
    __syncthreads();
    for (int k = 2; k <= NN; k <<= 1) {
        for (int j = k >> 1; j > 0; j >>= 1) {
            for (int i = t; i < NN; i += 1024) {
                int ix = i ^ j;
                if (ix > i) {
                    bool desc = ((i & k) == 0);
                    unsigned long long a = key[i], c = key[ix];
                    if (desc ? (a < c) : (a > c)) { key[i] = c; key[ix] = a; }
                }
            }
            __syncthreads();
        }
    }
    if (t < KK) {
        int idx = NN - 1 - (int)(key[t] & 0x7FFull);
        out_topi[b * KK + t] = (float)idx;
    }
    __shared__ float cutsh;
    if (t == 0) cutsh = __uint_as_float((unsigned)(key[KK - 1] >> 11));
    __syncthreads();
    float cut = cutsh;
    __shared__ int cnts[1024];
    int m0 = 2 * t, m1 = 2 * t + 1;
    float ca0 = fmaxf(g_alpha[b][m0] + 1e-07f - cut, 0.f);
    float ca1 = fmaxf(g_alpha[b][m1] + 1e-07f - cut, 0.f);
    g_ca[b][m0] = ca0; g_ca[b][m1] = ca1;
    int c = (ca0 > 0.f) + (ca1 > 0.f);
    cnts[t] = c;
    __syncthreads();
    for (int d = 1; d < 1024; d <<= 1) {
        int v = (t >= d) ? cnts[t - d] : 0;
        __syncthreads();
        cnts[t] += v;
        __syncthreads();
    }
    int off = cnts[t] - c;
    if (t == 1023) {
        int ns = cnts[1023];
        g_nsup[b] = (ns > KMAX) ? KMAX : ns;
    }
    int j = off;
    if (ca0 > 0.f) {
        if (j < KMAX) g_sup[b][j] = m0;
        g_colidx[b][m0] = (j < KMAX) ? j : -1;
        j++;
    } else g_colidx[b][m0] = -1;
    if (ca1 > 0.f) {
        if (j < KMAX) g_sup[b][j] = m1;
        g_colidx[b][m1] = (j < KMAX) ? j : -1;
    } else g_colidx[b][m1] = -1;
}

// ---- k4: build S row (register compose, dense write) + sparse Sc + invr ----
__global__ void k4_buildS(float* __restrict__ S_out) {
    int bid = blockIdx.x;
    int b = bid >> 11, n = bid & (NN - 1);
    int t = threadIdx.x;
    int wid = t >> 5, lane = t & 31;
    __shared__ int skk[LMAX + 1];
    __shared__ float sval[LMAX + 1];
    __shared__ float wsum[8];
    __shared__ int wsc[8];
    __shared__ int diagp;
    __shared__ float sdiagval;

    int cnt = g_adjcnt[b][n];
    float rf = g_rowfac[b][n];
    if (t == 0) diagp = 0;
    __syncthreads();
    int kk = -1; float aval = 0.f;
    bool isreal = (t < cnt);
    if (isreal) {
        kk = g_adjk[b][n][t];
        aval = g_adja[b][n][t];
        if (kk == n) diagp = 1;
    }
    __syncthreads();
    bool isvirt = (t == cnt) && !diagp;
    if (isreal && kk == n) aval += 1.0f;
    if (isvirt) { kk = n; aval = 1.0f; }
    float wv = (kk >= 0) ? rf * aval * g_dg[b][kk] * g_ca[b][kk] : 0.f;
    // block L1 sum
    float r = wv;
    #pragma unroll
    for (int o = 16; o > 0; o >>= 1) r += __shfl_down_sync(FULLM, r, o);
    if (lane == 0) wsum[wid] = r;
    __syncthreads();
    float tot = ((wsum[0] + wsum[1]) + (wsum[2] + wsum[3]))
              + ((wsum[4] + wsum[5]) + (wsum[6] + wsum[7]));
    float invr = 1.0f / fmaxf(tot, 1e-12f);
    if (t == 0) g_invr[b][n] = invr;
    float val = wv * invr;
    if (isreal) { skk[t] = kk; sval[t] = val; }
    if (isvirt) sdiagval = val;

    // sparse Sc row compaction (slots with colidx >= 0)
    int j = (kk >= 0) ? g_colidx[b][kk] : -1;
    bool p = (j >= 0);
    unsigned bal = __ballot_sync(FULLM, p);
    int wpre = __popc(bal & ((1u << lane) - 1));
    if (lane == 0) wsc[wid] = __popc(bal);
    __syncthreads();
    int sbase = 0;
    #pragma unroll
    for (int w = 0; w < 8; w++) sbase += (w < wid) ? wsc[w] : 0;
    if (p) {
        int pos = sbase + wpre;
        if (pos < SCAP) g_sent[b][n][pos] = make_uint2((unsigned)j, __float_as_uint(val));
    }
    if (t == 255) {
        int stot = wsc[0] + wsc[1] + wsc[2] + wsc[3] + wsc[4] + wsc[5] + wsc[6] + wsc[7];
        g_scnt[b][n] = (stot > SCAP) ? SCAP : stot;
    }
    __syncthreads();

    // register-compose two 4-col windows: [4t,4t+4) and [4t+1024,4t+1028)
    float4* drow = (float4*)(S_out + ((size_t)b * NN + n) * NN);
    bool hasdiag = !diagp;
    #pragma unroll
    for (int h = 0; h < 2; h++) {
        int w0 = 4 * t + h * 1024;
        float o4[4] = {0.f, 0.f, 0.f, 0.f};
        int lo = 0, hi = cnt;
        while (lo < hi) { int mid = (lo + hi) >> 1; if (skk[mid] < w0) lo = mid + 1; else hi = mid; }
        for (int q = lo; q < cnt; q++) {
            int c = skk[q];
            if (c >= w0 + 4) break;
            o4[c - w0] = sval[q];
        }
        if (hasdiag && n >= w0 && n < w0 + 4) o4[n - w0] = sdiagval;
        drow[t + h * 256] = make_float4(o4[0], o4[1], o4[2], o4[3]);
    }
}

// ---------------- k5: T = adj @ Sc (sparse x sparse, warp per row) ---------
__global__ void k5_T() {
    int gw = blockIdx.x * 8 + (threadIdx.x >> 5);
    int b = gw >> 11, n = gw & (NN - 1);
    int lane = threadIdx.x & 31;
    int cnt = g_adjcnt[b][n];
    float acc[8] = {0.f, 0.f, 0.f, 0.f, 0.f, 0.f, 0.f, 0.f};
    for (int i = 0; i < cnt; i++) {
        int k = g_adjk[b][n][i];
        float a = g_adja[b][n][i];
        int c = g_scnt[b][k];
        const uint2* ent = g_sent[b][k];
        for (int e = 0; e < c; e++) {
            uint2 pr = ent[e];
            int j = (int)pr.x;
            float av = a * __uint_as_float(pr.y);
            bool mine = (lane == (j & 31));
            int reg = j >> 5;
            #pragma unroll
            for (int rr = 0; rr < 8; rr++)
                if (mine && reg == rr) acc[rr] += av;
        }
    }
    #pragma unroll
    for (int rr = 0; rr < 8; rr++)
        g_T[b][n][rr * 32 + lane] = acc[rr];
}

// helper: weights of S column m (pattern = adjlist[m] (+diag), symmetric adj)
__device__ __forceinline__ int load_col_weights(int b, int m, int t,
                                                int* sk, float* sw, int* diagp) {
    int cnt = g_adjcnt[b][m];
    float colscale = g_dg[b][m] * g_ca[b][m];
    if (t == 0) *diagp = 0;
    __syncthreads();
    int kk = -1; float a = 0.f;
    if (t < cnt) {
        kk = g_adjk[b][m][t];
        a = g_adja[b][m][t];
        if (kk == m) *diagp = 1;
    }
    __syncthreads();
    if (t < cnt) {
        if (kk == m) a += 1.0f;
        sk[t] = kk;
        sw[t] = g_rowfac[b][kk] * a * colscale * g_invr[b][kk];
    }
    int tot = cnt + ((*diagp) ? 0 : 1);
    if (!(*diagp) && t == 0) {
        sk[cnt] = m;
        sw[cnt] = g_rowfac[b][m] * colscale * g_invr[b][m];
    }
    __syncthreads();
    return tot;
}

// ---------------- k6: x_c = S^T x, dense rows ----------------
__global__ void k6_xc(float* __restrict__ xc, const float* __restrict__ x) {
    int m = blockIdx.x, b = blockIdx.y;
    int t = threadIdx.x;
    float* orow = xc + ((size_t)b * NN + m) * FD;
    if (g_colidx[b][m] < 0) { orow[t] = 0.f; return; }
    __shared__ int sk[LMAX + 1];
    __shared__ float sw[LMAX + 1];
    __shared__ int diagp;
    int tot = load_col_weights(b, m, t, sk, sw, &diagp);
    float acc = 0.f;
    for (int i = 0; i < tot; i++)
        acc += sw[i] * x[((size_t)b * NN + sk[i]) * FD + t];
    orow[t] = acc;
}

// ---------------- k7: coarse = S^T T, register-compose dense rows ----------
__global__ void k7_coarse(float* __restrict__ coarse) {
    int m = blockIdx.x, b = blockIdx.y;
    int t = threadIdx.x;
    float4* orow = (float4*)(coarse + ((size_t)b * NN + m) * NN);
    if (g_colidx[b][m] < 0) {
        float4 z = make_float4(0.f, 0.f, 0.f, 0.f);
        orow[t] = z; orow[t + 256] = z;
        return;
    }
    int ns = g_nsup[b];
    __shared__ int sk[LMAX + 1];
    __shared__ float sw[LMAX + 1];
    __shared__ int diagp;
    __shared__ float vals[KMAX];
    __shared__ int ssup[KMAX];
    int tot = load_col_weights(b, m, t, sk, sw, &diagp);
    if (t < ns) {
        ssup[t] = g_sup[b][t];
        float acc = 0.f;
        for (int i = 0; i < tot; i++)
            acc += sw[i] * g_T[b][sk[i]][t];
        vals[t] = floorf(acc * 10000.0f) / 10000.0f;
    }
    __syncthreads();
    #pragma unroll
    for (int h = 0; h < 2; h++) {
        int w0 = 4 * t + h * 1024;
        float o4[4] = {0.f, 0.f, 0.f, 0.f};
        int lo = 0, hi = ns;
        while (lo < hi) { int mid = (lo + hi) >> 1; if (ssup[mid] < w0) lo = mid + 1; else hi = mid; }
        for (int q = lo; q < ns; q++) {
            int c = ssup[q];
            if (c >= w0 + 4) break;
            o4[c - w0] = vals[q];
        }
        orow[t + h * 256] = make_float4(o4[0], o4[1], o4[2], o4[3]);
    }
}

extern "C" void kernel_launch(void* const* d_in, const int* in_sizes, int n_in,
                              void* d_out, int out_size) {
    const float* x    = (const float*)d_in[0];
    const float* adj  = (const float*)d_in[1];
    const float* W    = (const float*)d_in[2];
    const float* bias = (const float*)d_in[3];
    float* out = (float*)d_out;

    kA_scan<<<BB * NN, 256>>>(x, adj, W);
    kB_alpha<<<BB * NN / 8, 256>>>(bias);
    k3_topk<<<BB, 1024>>>(out + TI_OFF);
    k4_buildS<<<BB * NN, 256>>>(out + S_OFF);
    k5_T<<<BB * NN / 8, 256>>>();
    k6_xc<<<dim3(NN, BB), 256>>>(out + XC_OFF, x);
    k7_coarse<<<dim3(NN, BB), 256>>>(out + CO_OFF);
}